// round 11
// baseline (speedup 1.0000x reference)
#include <cuda_runtime.h>
#include <cuda_bf16.h>

#define NUM_O 1024
#define THREADS 256
#define WARPS 8
#define GRID_BLOCKS 512
#define TOTAL_WARPS (GRID_BLOCKS * WARPS)   // 4096
#define RPW 4                                // rows per warp task
#define ROW_STRIDE (TOTAL_WARPS * RPW)       // 16384

#define RCP_CAP 65536
__device__ float g_rcp[RCP_CAP];             // 1/rowsum scratch (written fully by K1 each call)

__device__ __forceinline__ float ex2_(float x) {
    float y; asm("ex2.approx.ftz.f32 %0, %1;" : "=f"(y) : "f"(x)); return y;
}

// 4-coeff uniform-sigma fast path (verified R3-R10, rel_err ~2.6e-6):
//   c = exp(-2*ls)*log2e ; sg = -c*|mu|^2 ; s_k = c*(2*mu_k - 1) ; scx = -c
//   arg_true = sg + s0*x0+s1*x1+s2*x2 + scx*(xx-(x0+x1+x2))
// UNI: scx term is per-row constant -> cancels in normalization (dropped
// consistently in BOTH kernels); remaining arg <= 0 for x,mu in [0,1]^3.
__device__ __forceinline__ bool build_coeffs(
    float* sg, float* s0, float* s1, float* s2, float* scx,
    const float* __restrict__ mus, const float* __restrict__ log_sigmas)
{
    const float LOG2E = 1.4426950408889634f;
    const float ls0 = __ldg(&log_sigmas[0]);
    bool uni = true;
    for (int o = threadIdx.x; o < NUM_O; o += THREADS) {
        float ls = __ldg(&log_sigmas[o]);
        uni = uni && (ls == ls0);
        float m0 = mus[3*o + 0];
        float m1 = mus[3*o + 1];
        float m2 = mus[3*o + 2];
        float c = __expf(-2.0f * ls) * LOG2E;
        sg[o] = -c * (m0*m0 + m1*m1 + m2*m2);
        s0[o] = c * (2.0f * m0 - 1.0f);
        s1[o] = c * (2.0f * m1 - 1.0f);
        s2[o] = c * (2.0f * m2 - 1.0f);
        scx[o] = -c;
    }
    return uni;
}

__device__ __forceinline__ void load_x4(
    const float* __restrict__ x, int rbase, int rows,
    float* x0, float* x1, float* x2)
{
    if (rbase + RPW <= rows) {
        // rbase multiple of 4 -> offset 3*rbase floats is 16B-aligned.
        const float4* xp = reinterpret_cast<const float4*>(x + (size_t)rbase * 3);
        float4 u0 = __ldg(xp + 0), u1 = __ldg(xp + 1), u2 = __ldg(xp + 2);
        x0[0]=u0.x; x1[0]=u0.y; x2[0]=u0.z;
        x0[1]=u0.w; x1[1]=u1.x; x2[1]=u1.y;
        x0[2]=u1.z; x1[2]=u1.w; x2[2]=u2.x;
        x0[3]=u2.y; x1[3]=u2.z; x2[3]=u2.w;
    } else {
        #pragma unroll
        for (int r = 0; r < RPW; r++) {
            int rc = (rbase + r < rows) ? (rbase + r) : (rows - 1);
            x0[r] = __ldg(&x[rc*3+0]);
            x1[r] = __ldg(&x[rc*3+1]);
            x2[r] = __ldg(&x[rc*3+2]);
        }
    }
}

// ---------------- Kernel 1: row sums -> g_rcp ----------------
template<bool UNI>
__device__ __forceinline__ void run_sums(
    const float* __restrict__ sg, const float* __restrict__ s0,
    const float* __restrict__ s1, const float* __restrict__ s2,
    const float* __restrict__ scx,
    const float* __restrict__ x, int rows, int gwarp, int lane)
{
    const int olane = lane * 4;
    for (int rbase = gwarp * RPW; rbase < rows; rbase += ROW_STRIDE) {
        float x0[RPW], x1[RPW], x2[RPW];
        load_x4(x, rbase, rows, x0, x1, x2);
        float sxm[RPW];
        if (!UNI) {
            #pragma unroll
            for (int r = 0; r < RPW; r++)
                sxm[r] = (x0[r]*x0[r] + x1[r]*x1[r] + x2[r]*x2[r])
                         - (x0[r] + x1[r] + x2[r]);
        }

        float acc[RPW] = {0.f, 0.f, 0.f, 0.f};

        #pragma unroll
        for (int j = 0; j < 8; j++) {
            const int o = j * 128 + olane;
            const float4 G = *reinterpret_cast<const float4*>(sg + o);
            const float4 A = *reinterpret_cast<const float4*>(s0 + o);
            const float4 B = *reinterpret_cast<const float4*>(s1 + o);
            const float4 C = *reinterpret_cast<const float4*>(s2 + o);
            float4 S;
            if (!UNI) S = *reinterpret_cast<const float4*>(scx + o);

            #pragma unroll
            for (int r = 0; r < RPW; r++) {
                float b0 = G.x, b1 = G.y, b2 = G.z, b3 = G.w;
                if (!UNI) {
                    b0 = fmaf(S.x, sxm[r], b0); b1 = fmaf(S.y, sxm[r], b1);
                    b2 = fmaf(S.z, sxm[r], b2); b3 = fmaf(S.w, sxm[r], b3);
                }
                b0 = fmaf(C.x, x2[r], b0); b1 = fmaf(C.y, x2[r], b1);
                b2 = fmaf(C.z, x2[r], b2); b3 = fmaf(C.w, x2[r], b3);
                b0 = fmaf(B.x, x1[r], b0); b1 = fmaf(B.y, x1[r], b1);
                b2 = fmaf(B.z, x1[r], b2); b3 = fmaf(B.w, x1[r], b3);
                b0 = fmaf(A.x, x0[r], b0); b1 = fmaf(A.y, x0[r], b1);
                b2 = fmaf(A.z, x0[r], b2); b3 = fmaf(A.w, x0[r], b3);
                acc[r] += (ex2_(b0) + ex2_(b1)) + (ex2_(b2) + ex2_(b3));
            }
        }

        #pragma unroll
        for (int r = 0; r < RPW; r++) {
            float s = acc[r];
            #pragma unroll
            for (int off = 16; off > 0; off >>= 1)
                s += __shfl_xor_sync(0xFFFFFFFFu, s, off);
            if (lane == r && rbase + r < rows)
                g_rcp[rbase + r] = 1.0f / s;
        }
    }
}

__global__ void __launch_bounds__(THREADS, 4)
rbf_sums_kernel(const float* __restrict__ x,
                const float* __restrict__ mus,
                const float* __restrict__ log_sigmas,
                int rows)
{
    __shared__ __align__(16) float sg[NUM_O], s0[NUM_O], s1[NUM_O], s2[NUM_O], scx[NUM_O];
    bool uni = build_coeffs(sg, s0, s1, s2, scx, mus, log_sigmas);
    int uall = __syncthreads_and(uni ? 1 : 0);

    const int lane  = threadIdx.x & 31;
    const int gwarp = blockIdx.x * WARPS + (threadIdx.x >> 5);
    if (uall) run_sums<true >(sg, s0, s1, s2, scx, x, rows, gwarp, lane);
    else      run_sums<false>(sg, s0, s1, s2, scx, x, rows, gwarp, lane);
}

// ---------------- Kernel 2: recompute, normalize, store ----------------
template<bool UNI>
__device__ __forceinline__ void run_norm(
    const float* __restrict__ sg, const float* __restrict__ s0,
    const float* __restrict__ s1, const float* __restrict__ s2,
    const float* __restrict__ scx,
    const float* __restrict__ x, float* __restrict__ out,
    int rows, int gwarp, int lane)
{
    const int olane = lane * 4;
    for (int rbase = gwarp * RPW; rbase < rows; rbase += ROW_STRIDE) {
        float x0[RPW], x1[RPW], x2[RPW];
        load_x4(x, rbase, rows, x0, x1, x2);
        float sxm[RPW];
        if (!UNI) {
            #pragma unroll
            for (int r = 0; r < RPW; r++)
                sxm[r] = (x0[r]*x0[r] + x1[r]*x1[r] + x2[r]*x2[r])
                         - (x0[r] + x1[r] + x2[r]);
        }
        float rcp[RPW];
        #pragma unroll
        for (int r = 0; r < RPW; r++) {
            int rc = (rbase + r < rows) ? (rbase + r) : (rows - 1);
            rcp[r] = __ldg(&g_rcp[rc]);
        }

        float* orow = out + (size_t)rbase * NUM_O + olane;
        const bool full = (rbase + RPW <= rows);

        #pragma unroll
        for (int j = 0; j < 8; j++) {
            const int o = j * 128 + olane;
            const float4 G = *reinterpret_cast<const float4*>(sg + o);
            const float4 A = *reinterpret_cast<const float4*>(s0 + o);
            const float4 B = *reinterpret_cast<const float4*>(s1 + o);
            const float4 C = *reinterpret_cast<const float4*>(s2 + o);
            float4 S;
            if (!UNI) S = *reinterpret_cast<const float4*>(scx + o);

            #pragma unroll
            for (int r = 0; r < RPW; r++) {
                float b0 = G.x, b1 = G.y, b2 = G.z, b3 = G.w;
                if (!UNI) {
                    b0 = fmaf(S.x, sxm[r], b0); b1 = fmaf(S.y, sxm[r], b1);
                    b2 = fmaf(S.z, sxm[r], b2); b3 = fmaf(S.w, sxm[r], b3);
                }
                b0 = fmaf(C.x, x2[r], b0); b1 = fmaf(C.y, x2[r], b1);
                b2 = fmaf(C.z, x2[r], b2); b3 = fmaf(C.w, x2[r], b3);
                b0 = fmaf(B.x, x1[r], b0); b1 = fmaf(B.y, x1[r], b1);
                b2 = fmaf(B.z, x1[r], b2); b3 = fmaf(B.w, x1[r], b3);
                b0 = fmaf(A.x, x0[r], b0); b1 = fmaf(A.y, x0[r], b1);
                b2 = fmaf(A.z, x0[r], b2); b3 = fmaf(A.w, x0[r], b3);

                float4 v;
                v.x = ex2_(b0) * rcp[r];
                v.y = ex2_(b1) * rcp[r];
                v.z = ex2_(b2) * rcp[r];
                v.w = ex2_(b3) * rcp[r];
                if (full || rbase + r < rows)
                    *reinterpret_cast<float4*>(orow + (size_t)r * NUM_O + j * 128) = v;
            }
        }
    }
}

__global__ void __launch_bounds__(THREADS, 4)
rbf_norm_kernel(const float* __restrict__ x,
                const float* __restrict__ mus,
                const float* __restrict__ log_sigmas,
                float* __restrict__ out,
                int rows)
{
    __shared__ __align__(16) float sg[NUM_O], s0[NUM_O], s1[NUM_O], s2[NUM_O], scx[NUM_O];
    bool uni = build_coeffs(sg, s0, s1, s2, scx, mus, log_sigmas);
    int uall = __syncthreads_and(uni ? 1 : 0);

    const int lane  = threadIdx.x & 31;
    const int gwarp = blockIdx.x * WARPS + (threadIdx.x >> 5);
    if (uall) run_norm<true >(sg, s0, s1, s2, scx, x, out, rows, gwarp, lane);
    else      run_norm<false>(sg, s0, s1, s2, scx, x, out, rows, gwarp, lane);
}

extern "C" void kernel_launch(void* const* d_in, const int* in_sizes, int n_in,
                              void* d_out, int out_size) {
    const float* x          = (const float*)d_in[0];  // (B,S,3)
    const float* mus        = (const float*)d_in[1];  // (1024,3)
    const float* log_sigmas = (const float*)d_in[2];  // (1024,)
    float* out = (float*)d_out;

    const int rows = in_sizes[0] / 3;  // B*S (32768 for this dataset; cap 65536)
    rbf_sums_kernel<<<GRID_BLOCKS, THREADS>>>(x, mus, log_sigmas, rows);
    rbf_norm_kernel<<<GRID_BLOCKS, THREADS>>>(x, mus, log_sigmas, out, rows);
}

// round 12
// speedup vs baseline: 2.9793x; 2.9793x over previous
#include <cuda_runtime.h>
#include <cuda_bf16.h>

#define NUM_O 1024
#define THREADS 256
#define WARPS 8
#define BLOCKS_PER_SM 3
#define GRID_BLOCKS (148 * BLOCKS_PER_SM)   // 444, one persistent wave
#define TOTAL_WARPS (GRID_BLOCKS * WARPS)   // 3552

__device__ __forceinline__ float ex2_(float x) {
    float y; asm("ex2.approx.ftz.f32 %0, %1;" : "=f"(y) : "f"(x)); return y;
}

// 4-coeff uniform-sigma fast path (verified R3-R11, rel_err ~2.6e-6):
//   c = exp(-2*ls)*log2e ; sg = -c*|mu|^2 ; s_k = c*(2*mu_k - 1) ; scx = -c
//   arg_true = sg + s0*x0+s1*x1+s2*x2 + scx*(xx-(x0+x1+x2))
// UNI: scx term is per-row constant -> cancels in normalization; remaining
// arg <= 0 for x,mu in [0,1]^3 (no overflow).
template<bool UNI>
__device__ __forceinline__ void run_rows(
    const float* __restrict__ sg, const float* __restrict__ s0,
    const float* __restrict__ s1, const float* __restrict__ s2,
    const float* __restrict__ scx,
    const float* __restrict__ x, float* __restrict__ out,
    int rows, int gwarp, int lane)
{
    int row = gwarp;
    if (row >= rows) return;

    const int olane = lane * 4;

    // x prefetch pipeline: current row's x loaded before the loop.
    float xc0 = __ldg(&x[row*3+0]);
    float xc1 = __ldg(&x[row*3+1]);
    float xc2 = __ldg(&x[row*3+2]);

    for (; row < rows; row += TOTAL_WARPS) {
        // Issue next row's x loads now; consumed next iteration.
        float xn0, xn1, xn2;
        {
            int nr = row + TOTAL_WARPS;
            int nc = (nr < rows) ? nr : row;
            xn0 = __ldg(&x[nc*3+0]);
            xn1 = __ldg(&x[nc*3+1]);
            xn2 = __ldg(&x[nc*3+2]);
        }

        const float x0 = xc0, x1 = xc1, x2 = xc2;
        float sxm;
        if (!UNI) sxm = (x0*x0 + x1*x1 + x2*x2) - (x0 + x1 + x2);

        float e[32];
        float acc0 = 0.f, acc1 = 0.f;

        // Coefficient double-buffer: j+1's loads issue before j's math.
        float4 G = *reinterpret_cast<const float4*>(sg + olane);
        float4 A = *reinterpret_cast<const float4*>(s0 + olane);
        float4 B = *reinterpret_cast<const float4*>(s1 + olane);
        float4 C = *reinterpret_cast<const float4*>(s2 + olane);
        float4 S;
        if (!UNI) S = *reinterpret_cast<const float4*>(scx + olane);

        #pragma unroll
        for (int j = 0; j < 8; j++) {
            float4 Gn, An, Bn, Cn, Sn;
            if (j < 7) {
                const int on = (j + 1) * 128 + olane;
                Gn = *reinterpret_cast<const float4*>(sg + on);
                An = *reinterpret_cast<const float4*>(s0 + on);
                Bn = *reinterpret_cast<const float4*>(s1 + on);
                Cn = *reinterpret_cast<const float4*>(s2 + on);
                if (!UNI) Sn = *reinterpret_cast<const float4*>(scx + on);
            }

            float b0 = G.x, b1 = G.y, b2 = G.z, b3 = G.w;
            if (!UNI) {
                b0 = fmaf(S.x, sxm, b0); b1 = fmaf(S.y, sxm, b1);
                b2 = fmaf(S.z, sxm, b2); b3 = fmaf(S.w, sxm, b3);
            }
            b0 = fmaf(C.x, x2, b0); b1 = fmaf(C.y, x2, b1);
            b2 = fmaf(C.z, x2, b2); b3 = fmaf(C.w, x2, b3);
            b0 = fmaf(B.x, x1, b0); b1 = fmaf(B.y, x1, b1);
            b2 = fmaf(B.z, x1, b2); b3 = fmaf(B.w, x1, b3);
            b0 = fmaf(A.x, x0, b0); b1 = fmaf(A.y, x0, b1);
            b2 = fmaf(A.z, x0, b2); b3 = fmaf(A.w, x0, b3);

            const float v0 = ex2_(b0), v1 = ex2_(b1), v2 = ex2_(b2), v3 = ex2_(b3);
            e[j*4+0] = v0; e[j*4+1] = v1; e[j*4+2] = v2; e[j*4+3] = v3;
            acc0 += (v0 + v1); acc1 += (v2 + v3);

            if (j < 7) { G = Gn; A = An; B = Bn; C = Cn; if (!UNI) S = Sn; }
        }

        float acc = acc0 + acc1;
        #pragma unroll
        for (int off = 16; off > 0; off >>= 1)
            acc += __shfl_xor_sync(0xFFFFFFFFu, acc, off);
        const float rcp = 1.0f / acc;

        float* orow = out + (size_t)row * NUM_O + olane;
        #pragma unroll
        for (int j = 0; j < 8; j++) {
            float4 v;
            v.x = e[j*4+0] * rcp; v.y = e[j*4+1] * rcp;
            v.z = e[j*4+2] * rcp; v.w = e[j*4+3] * rcp;
            *reinterpret_cast<float4*>(orow + j * 128) = v;
        }

        xc0 = xn0; xc1 = xn1; xc2 = xn2;
    }
}

__global__ void __launch_bounds__(THREADS, BLOCKS_PER_SM)
gaussian_rbf_kernel(const float* __restrict__ x,
                    const float* __restrict__ mus,
                    const float* __restrict__ log_sigmas,
                    float* __restrict__ out,
                    int rows)
{
    __shared__ __align__(16) float sg[NUM_O];
    __shared__ __align__(16) float s0[NUM_O];
    __shared__ __align__(16) float s1[NUM_O];
    __shared__ __align__(16) float s2[NUM_O];
    __shared__ __align__(16) float scx[NUM_O];

    const float LOG2E = 1.4426950408889634f;
    const float ls0 = __ldg(&log_sigmas[0]);
    bool uni = true;

    for (int o = threadIdx.x; o < NUM_O; o += THREADS) {
        float ls = __ldg(&log_sigmas[o]);
        uni = uni && (ls == ls0);
        float m0 = mus[3*o + 0];
        float m1 = mus[3*o + 1];
        float m2 = mus[3*o + 2];
        float c = __expf(-2.0f * ls) * LOG2E;
        sg[o] = -c * (m0*m0 + m1*m1 + m2*m2);
        s0[o] = c * (2.0f * m0 - 1.0f);
        s1[o] = c * (2.0f * m1 - 1.0f);
        s2[o] = c * (2.0f * m2 - 1.0f);
        scx[o] = -c;
    }
    int uall = __syncthreads_and(uni ? 1 : 0);
    // No further block-wide synchronization: warps proceed independently.

    const int warp  = threadIdx.x >> 5;
    const int lane  = threadIdx.x & 31;
    const int gwarp = blockIdx.x * WARPS + warp;

    if (uall)
        run_rows<true >(sg, s0, s1, s2, scx, x, out, rows, gwarp, lane);
    else
        run_rows<false>(sg, s0, s1, s2, scx, x, out, rows, gwarp, lane);
}

extern "C" void kernel_launch(void* const* d_in, const int* in_sizes, int n_in,
                              void* d_out, int out_size) {
    const float* x          = (const float*)d_in[0];  // (B,S,3)
    const float* mus        = (const float*)d_in[1];  // (1024,3)
    const float* log_sigmas = (const float*)d_in[2];  // (1024,)
    float* out = (float*)d_out;

    const int rows = in_sizes[0] / 3;  // B*S
    gaussian_rbf_kernel<<<GRID_BLOCKS, THREADS>>>(x, mus, log_sigmas, out, rows);
}

// round 14
// speedup vs baseline: 2.9989x; 1.0066x over previous
#include <cuda_runtime.h>
#include <cuda_bf16.h>

#define NUM_O 1024
#define THREADS 256            // each thread owns 4 output columns: o = tid*4
#define RPT 8                  // rows per tile
#define BLOCKS_PER_SM 3
#define GRID_BLOCKS (148 * BLOCKS_PER_SM)

__device__ __forceinline__ float ex2_(float x) {
    float y; asm("ex2.approx.ftz.f32 %0, %1;" : "=f"(y) : "f"(x)); return y;
}

// 4-coeff uniform-sigma fast path (verified R3-R12, rel_err ~2.6e-6):
//   c = exp(-2*ls)*log2e ; sg = -c*|mu|^2 ; s_k = c*(2*mu_k - 1) ; scx = -c
//   arg_true = sg + s0*x0+s1*x1+s2*x2 + scx*(xx-(x0+x1+x2))
// UNI: scx term is per-row constant -> cancels in normalization; remaining
// arg <= 0 for x,mu in [0,1]^3 (no overflow).
template<bool UNI>
__device__ __forceinline__ void run_tiles(
    float4 G, float4 A, float4 B, float4 C, float4 S,
    float (*xs)[RPT * 3], float (*wsum)[8], float* rcp_s,
    const float* __restrict__ x, float* __restrict__ out,
    int rows, int tiles, int tid, int warp, int lane)
{
    const int xmax = rows * 3 - 1;
    int buf = 0;

    // Preload first tile's x into smem buffer 0.
    {
        int t0 = blockIdx.x;
        if (tid < RPT * 3) {
            int idx = t0 * (RPT * 3) + tid;
            xs[0][tid] = __ldg(&x[idx <= xmax ? idx : xmax]);
        }
    }
    __syncthreads();

    for (int t = blockIdx.x; t < tiles; t += GRID_BLOCKS, buf ^= 1) {
        const int rbase = t * RPT;

        float e[RPT][4];
        float acc[RPT];

        #pragma unroll
        for (int r = 0; r < RPT; r++) {
            const float x0 = xs[buf][r*3+0];
            const float x1 = xs[buf][r*3+1];
            const float x2 = xs[buf][r*3+2];

            float b0 = G.x, b1 = G.y, b2 = G.z, b3 = G.w;
            if (!UNI) {
                float sxm = (x0*x0 + x1*x1 + x2*x2) - (x0 + x1 + x2);
                b0 = fmaf(S.x, sxm, b0); b1 = fmaf(S.y, sxm, b1);
                b2 = fmaf(S.z, sxm, b2); b3 = fmaf(S.w, sxm, b3);
            }
            b0 = fmaf(C.x, x2, b0); b1 = fmaf(C.y, x2, b1);
            b2 = fmaf(C.z, x2, b2); b3 = fmaf(C.w, x2, b3);
            b0 = fmaf(B.x, x1, b0); b1 = fmaf(B.y, x1, b1);
            b2 = fmaf(B.z, x1, b2); b3 = fmaf(B.w, x1, b3);
            b0 = fmaf(A.x, x0, b0); b1 = fmaf(A.y, x0, b1);
            b2 = fmaf(A.z, x0, b2); b3 = fmaf(A.w, x0, b3);

            const float v0 = ex2_(b0), v1 = ex2_(b1), v2 = ex2_(b2), v3 = ex2_(b3);
            e[r][0] = v0; e[r][1] = v1; e[r][2] = v2; e[r][3] = v3;
            acc[r] = (v0 + v1) + (v2 + v3);
        }

        // Stage 1: per-row intra-warp reduction; lane r writes row r's partial.
        #pragma unroll
        for (int r = 0; r < RPT; r++) {
            float s = acc[r];
            #pragma unroll
            for (int off = 16; off > 0; off >>= 1)
                s += __shfl_xor_sync(0xFFFFFFFFu, s, off);
            if (lane == r) wsum[r][warp] = s;
        }

        // Prefetch next tile's x into the other buffer (overlaps stage 2).
        {
            int nt = t + GRID_BLOCKS;
            if (tid < RPT * 3) {
                int idx = nt * (RPT * 3) + tid;
                xs[buf ^ 1][tid] = __ldg(&x[idx <= xmax ? idx : xmax]);
            }
        }
        __syncthreads();   // A: wsum visible

        // Stage 2: 64 partials (8 rows x 8 warps) need TWO warps:
        // warp w (w<2) reduces rows 4w .. 4w+3, one 8-lane segment per row.
        if (warp < 2) {
            const int row = warp * 4 + (lane >> 3);
            float v = wsum[row][lane & 7];
            v += __shfl_xor_sync(0xFFFFFFFFu, v, 1);
            v += __shfl_xor_sync(0xFFFFFFFFu, v, 2);
            v += __shfl_xor_sync(0xFFFFFFFFu, v, 4);
            if ((lane & 7) == 0) rcp_s[row] = 1.0f / v;
        }
        __syncthreads();   // B: rcp visible

        // Normalize + store (each thread: 1 float4 per row).
        float* orow = out + (size_t)rbase * NUM_O + tid * 4;
        const bool full = (rbase + RPT <= rows);
        #pragma unroll
        for (int r = 0; r < RPT; r++, orow += NUM_O) {
            if (!full && rbase + r >= rows) break;
            const float rc = rcp_s[r];
            float4 v;
            v.x = e[r][0] * rc; v.y = e[r][1] * rc;
            v.z = e[r][2] * rc; v.w = e[r][3] * rc;
            *reinterpret_cast<float4*>(orow) = v;
        }
    }
}

__global__ void __launch_bounds__(THREADS, BLOCKS_PER_SM)
gaussian_rbf_kernel(const float* __restrict__ x,
                    const float* __restrict__ mus,
                    const float* __restrict__ log_sigmas,
                    float* __restrict__ out,
                    int rows)
{
    __shared__ __align__(16) float xs[2][RPT * 3];
    __shared__ float wsum[RPT][8];
    __shared__ float rcp_s[RPT];

    const int tid  = threadIdx.x;
    const int warp = tid >> 5;
    const int lane = tid & 31;

    // --- Per-thread coefficients for columns o = tid*4 .. tid*4+3 (registers) ---
    const float LOG2E = 1.4426950408889634f;
    const float ls0 = __ldg(&log_sigmas[0]);

    const float4* mp = reinterpret_cast<const float4*>(mus + (size_t)tid * 12);
    float4 M0 = __ldg(mp + 0), M1 = __ldg(mp + 1), M2 = __ldg(mp + 2);
    float4 LS = __ldg(reinterpret_cast<const float4*>(log_sigmas + (size_t)tid * 4));

    bool uni = (LS.x == ls0) & (LS.y == ls0) & (LS.z == ls0) & (LS.w == ls0);
    int uall = __syncthreads_and(uni ? 1 : 0);

    float m0[4] = {M0.x, M0.w, M1.z, M2.y};
    float m1[4] = {M0.y, M1.x, M1.w, M2.z};
    float m2[4] = {M0.z, M1.y, M2.x, M2.w};
    float lsv[4] = {LS.x, LS.y, LS.z, LS.w};

    float4 G, A, B, C, S;
    float* Gp = &G.x; float* Ap = &A.x; float* Bp = &B.x;
    float* Cp = &C.x; float* Sp = &S.x;
    #pragma unroll
    for (int k = 0; k < 4; k++) {
        float c = __expf(-2.0f * lsv[k]) * LOG2E;
        Gp[k] = -c * (m0[k]*m0[k] + m1[k]*m1[k] + m2[k]*m2[k]);
        Ap[k] = c * (2.0f * m0[k] - 1.0f);
        Bp[k] = c * (2.0f * m1[k] - 1.0f);
        Cp[k] = c * (2.0f * m2[k] - 1.0f);
        Sp[k] = -c;
    }

    const int tiles = (rows + RPT - 1) / RPT;

    if (uall)
        run_tiles<true >(G, A, B, C, S, xs, wsum, rcp_s, x, out, rows, tiles, tid, warp, lane);
    else
        run_tiles<false>(G, A, B, C, S, xs, wsum, rcp_s, x, out, rows, tiles, tid, warp, lane);
}

extern "C" void kernel_launch(void* const* d_in, const int* in_sizes, int n_in,
                              void* d_out, int out_size) {
    const float* x          = (const float*)d_in[0];  // (B,S,3)
    const float* mus        = (const float*)d_in[1];  // (1024,3)
    const float* log_sigmas = (const float*)d_in[2];  // (1024,)
    float* out = (float*)d_out;

    const int rows = in_sizes[0] / 3;  // B*S
    gaussian_rbf_kernel<<<GRID_BLOCKS, THREADS>>>(x, mus, log_sigmas, out, rows);
}

// round 16
// speedup vs baseline: 3.2329x; 1.0780x over previous
#include <cuda_runtime.h>
#include <cuda_bf16.h>

#define NUM_O 1024
#define THREADS 256            // each thread owns 4 output columns: o = tid*4
#define RPT 8                  // rows per tile
#define BLOCKS_PER_SM 3
#define GRID_BLOCKS (148 * BLOCKS_PER_SM)

__device__ __forceinline__ float ex2_(float x) {
    float y; asm("ex2.approx.ftz.f32 %0, %1;" : "=f"(y) : "f"(x)); return y;
}
__device__ __forceinline__ float rcp_(float x) {
    float y; asm("rcp.approx.ftz.f32 %0, %1;" : "=f"(y) : "f"(x)); return y;
}

// 4-coeff uniform-sigma fast path (verified R3-R14, rel_err ~2.6e-6):
//   c = exp(-2*ls)*log2e ; sg = -c*|mu|^2 ; s_k = c*(2*mu_k - 1) ; scx = -c
//   arg_true = sg + s0*x0+s1*x1+s2*x2 + scx*(xx-(x0+x1+x2))
// UNI: scx term is per-row constant -> cancels in normalization; remaining
// arg <= 0 for x,mu in [0,1]^3 (no overflow).
template<bool UNI>
__device__ __forceinline__ void run_tiles(
    float4 G, float4 A, float4 B, float4 C, float4 S,
    float (*xs)[RPT * 3], float (*wsum)[8],
    const float* __restrict__ x, float* __restrict__ out,
    int rows, int tiles, int tid, int warp, int lane)
{
    const int xmax = rows * 3 - 1;
    int buf = 0;

    // Preload first tile's x into smem buffer 0.
    {
        int t0 = blockIdx.x;
        if (tid < RPT * 3) {
            int idx = t0 * (RPT * 3) + tid;
            xs[0][tid] = __ldg(&x[idx <= xmax ? idx : xmax]);
        }
    }
    __syncthreads();

    for (int t = blockIdx.x; t < tiles; t += GRID_BLOCKS, buf ^= 1) {
        const int rbase = t * RPT;

        float e[RPT][4];
        float acc[RPT];

        #pragma unroll
        for (int r = 0; r < RPT; r++) {
            const float x0 = xs[buf][r*3+0];
            const float x1 = xs[buf][r*3+1];
            const float x2 = xs[buf][r*3+2];

            float b0 = G.x, b1 = G.y, b2 = G.z, b3 = G.w;
            if (!UNI) {
                float sxm = (x0*x0 + x1*x1 + x2*x2) - (x0 + x1 + x2);
                b0 = fmaf(S.x, sxm, b0); b1 = fmaf(S.y, sxm, b1);
                b2 = fmaf(S.z, sxm, b2); b3 = fmaf(S.w, sxm, b3);
            }
            b0 = fmaf(C.x, x2, b0); b1 = fmaf(C.y, x2, b1);
            b2 = fmaf(C.z, x2, b2); b3 = fmaf(C.w, x2, b3);
            b0 = fmaf(B.x, x1, b0); b1 = fmaf(B.y, x1, b1);
            b2 = fmaf(B.z, x1, b2); b3 = fmaf(B.w, x1, b3);
            b0 = fmaf(A.x, x0, b0); b1 = fmaf(A.y, x0, b1);
            b2 = fmaf(A.z, x0, b2); b3 = fmaf(A.w, x0, b3);

            const float v0 = ex2_(b0), v1 = ex2_(b1), v2 = ex2_(b2), v3 = ex2_(b3);
            e[r][0] = v0; e[r][1] = v1; e[r][2] = v2; e[r][3] = v3;
            acc[r] = (v0 + v1) + (v2 + v3);
        }

        // Stage 1: folded multi-row butterfly. Rows fold into lane bits
        // (xor 16 -> +4, xor 8 -> +2, xor 4 -> +1); after two plain stages,
        // lane l holds the warp total for row (l>>2)&7.
        #pragma unroll
        for (int r = 0; r < 4; r++) {
            const bool hi = (lane & 16);
            const float keep = hi ? acc[r+4] : acc[r];
            const float send = hi ? acc[r]   : acc[r+4];
            acc[r] = keep + __shfl_xor_sync(0xFFFFFFFFu, send, 16);
        }
        #pragma unroll
        for (int r = 0; r < 2; r++) {
            const bool hi = (lane & 8);
            const float keep = hi ? acc[r+2] : acc[r];
            const float send = hi ? acc[r]   : acc[r+2];
            acc[r] = keep + __shfl_xor_sync(0xFFFFFFFFu, send, 8);
        }
        {
            const bool hi = (lane & 4);
            const float keep = hi ? acc[1] : acc[0];
            const float send = hi ? acc[0] : acc[1];
            acc[0] = keep + __shfl_xor_sync(0xFFFFFFFFu, send, 4);
        }
        acc[0] += __shfl_xor_sync(0xFFFFFFFFu, acc[0], 2);
        acc[0] += __shfl_xor_sync(0xFFFFFFFFu, acc[0], 1);
        if ((lane & 3) == 0) wsum[lane >> 2][warp] = acc[0];

        // Prefetch next tile's x into the other buffer (overlaps barrier).
        {
            int nt = t + GRID_BLOCKS;
            if (tid < RPT * 3) {
                int idx = nt * (RPT * 3) + tid;
                xs[buf ^ 1][tid] = __ldg(&x[idx <= xmax ? idx : xmax]);
            }
        }
        __syncthreads();   // A: wsum visible (the ONLY barrier per tile)

        // Stage 2: every warp self-serves (no second barrier, no idle warps).
        // lane: row = lane>>2, reads 2 of row's 8 warp-partials as float2.
        float rr[RPT];
        {
            const float2 w2 = *reinterpret_cast<const float2*>(
                &wsum[lane >> 2][(lane & 3) * 2]);
            float p = w2.x + w2.y;
            p += __shfl_xor_sync(0xFFFFFFFFu, p, 1);
            p += __shfl_xor_sync(0xFFFFFFFFu, p, 2);
            const float rc = rcp_(p);          // lane holds rcp(row lane>>2)
            #pragma unroll
            for (int r = 0; r < RPT; r++)
                rr[r] = __shfl_sync(0xFFFFFFFFu, rc, r << 2);
        }

        // Normalize + store (each thread: 1 float4 per row).
        float* orow = out + (size_t)rbase * NUM_O + tid * 4;
        const bool full = (rbase + RPT <= rows);
        #pragma unroll
        for (int r = 0; r < RPT; r++, orow += NUM_O) {
            if (!full && rbase + r >= rows) break;
            float4 v;
            v.x = e[r][0] * rr[r]; v.y = e[r][1] * rr[r];
            v.z = e[r][2] * rr[r]; v.w = e[r][3] * rr[r];
            *reinterpret_cast<float4*>(orow) = v;
        }
    }
}

__global__ void __launch_bounds__(THREADS, BLOCKS_PER_SM)
gaussian_rbf_kernel(const float* __restrict__ x,
                    const float* __restrict__ mus,
                    const float* __restrict__ log_sigmas,
                    float* __restrict__ out,
                    int rows)
{
    __shared__ __align__(16) float xs[2][RPT * 3];
    __shared__ __align__(8) float wsum[RPT][8];

    const int tid  = threadIdx.x;
    const int warp = tid >> 5;
    const int lane = tid & 31;

    // --- Per-thread coefficients for columns o = tid*4 .. tid*4+3 (registers) ---
    const float LOG2E = 1.4426950408889634f;
    const float ls0 = __ldg(&log_sigmas[0]);

    const float4* mp = reinterpret_cast<const float4*>(mus + (size_t)tid * 12);
    float4 M0 = __ldg(mp + 0), M1 = __ldg(mp + 1), M2 = __ldg(mp + 2);
    float4 LS = __ldg(reinterpret_cast<const float4*>(log_sigmas + (size_t)tid * 4));

    bool uni = (LS.x == ls0) & (LS.y == ls0) & (LS.z == ls0) & (LS.w == ls0);
    int uall = __syncthreads_and(uni ? 1 : 0);

    float m0[4] = {M0.x, M0.w, M1.z, M2.y};
    float m1[4] = {M0.y, M1.x, M1.w, M2.z};
    float m2[4] = {M0.z, M1.y, M2.x, M2.w};
    float lsv[4] = {LS.x, LS.y, LS.z, LS.w};

    float4 G, A, B, C, S;
    float* Gp = &G.x; float* Ap = &A.x; float* Bp = &B.x;
    float* Cp = &C.x; float* Sp = &S.x;
    #pragma unroll
    for (int k = 0; k < 4; k++) {
        float c = __expf(-2.0f * lsv[k]) * LOG2E;
        Gp[k] = -c * (m0[k]*m0[k] + m1[k]*m1[k] + m2[k]*m2[k]);
        Ap[k] = c * (2.0f * m0[k] - 1.0f);
        Bp[k] = c * (2.0f * m1[k] - 1.0f);
        Cp[k] = c * (2.0f * m2[k] - 1.0f);
        Sp[k] = -c;
    }

    const int tiles = (rows + RPT - 1) / RPT;

    if (uall)
        run_tiles<true >(G, A, B, C, S, xs, wsum, x, out, rows, tiles, tid, warp, lane);
    else
        run_tiles<false>(G, A, B, C, S, xs, wsum, x, out, rows, tiles, tid, warp, lane);
}

extern "C" void kernel_launch(void* const* d_in, const int* in_sizes, int n_in,
                              void* d_out, int out_size) {
    const float* x          = (const float*)d_in[0];  // (B,S,3)
    const float* mus        = (const float*)d_in[1];  // (1024,3)
    const float* log_sigmas = (const float*)d_in[2];  // (1024,)
    float* out = (float*)d_out;

    const int rows = in_sizes[0] / 3;  // B*S
    gaussian_rbf_kernel<<<GRID_BLOCKS, THREADS>>>(x, mus, log_sigmas, out, rows);
}